// round 16
// baseline (speedup 1.0000x reference)
#include <cuda_runtime.h>
#include <cuda_bf16.h>
#include <cuda_fp16.h>
#include <cstdint>
#include <math.h>

#define DIM  2048
#define NH   16
#define NKV  4
#define HD   128
#define GRP  (NH / NKV)
#define TSEQ 2048
#define BMAX 2
#define QKVW (DIM + 2 * NKV * HD)   // 3072

// ---------------- scratch (device globals; no allocation allowed) ----------
__device__ __half g_wqkv_f[QKVW * DIM];              // rows: Q(2048) | K(512) | V(512)
__device__ __half g_wp_f[DIM * DIM];
__device__ __half g_a_f[BMAX * TSEQ * DIM];          // fp16 activations (x, then y)
__device__ float g_qkv[BMAX * TSEQ * QKVW];          // [bt][Q|K|V]
__device__ float g_vn[BMAX * TSEQ * NKV * HD];
__device__ float g_ropec[TSEQ * (HD / 2)];
__device__ float g_ropes[TSEQ * (HD / 2)];
__device__ __nv_bfloat16 g_qh[BMAX * NH * TSEQ * HD];
__device__ __nv_bfloat16 g_ql[BMAX * NH * TSEQ * HD];
__device__ __nv_bfloat16 g_kh[BMAX * NKV * TSEQ * HD];
__device__ __nv_bfloat16 g_kl[BMAX * NKV * TSEQ * HD];
__device__ __nv_bfloat16 g_vth[BMAX * NKV * HD * TSEQ];
__device__ __nv_bfloat16 g_vtl[BMAX * NKV * HD * TSEQ];

__device__ __forceinline__ void split_bf16(float v, __nv_bfloat16& h, __nv_bfloat16& l) {
    h = __float2bfloat16_rn(v);
    l = __float2bfloat16_rn(v - __bfloat162float(h));
}

__device__ __forceinline__ void split2_u32(float x, float y, uint32_t& h, uint32_t& l) {
    __nv_bfloat162 hh = __floats2bfloat162_rn(x, y);
    float rx = x - __bfloat162float(hh.x);
    float ry = y - __bfloat162float(hh.y);
    __nv_bfloat162 ll = __floats2bfloat162_rn(rx, ry);
    h = *(uint32_t*)&hh;
    l = *(uint32_t*)&ll;
}

// ---------------- async copy / ldmatrix / mma helpers ------------------------
__device__ __forceinline__ uint32_t smem_u32(const void* p) {
    return (uint32_t)__cvta_generic_to_shared(p);
}
__device__ __forceinline__ void cp16(void* s, const void* g) {
    asm volatile("cp.async.cg.shared.global [%0], [%1], 16;\n"
                 :: "r"(smem_u32(s)), "l"(g));
}
__device__ __forceinline__ void cp_commit() {
    asm volatile("cp.async.commit_group;\n");
}
template <int N>
__device__ __forceinline__ void cp_wait() {
    asm volatile("cp.async.wait_group %0;\n" :: "n"(N));
}
template <typename T>
__device__ __forceinline__ void ldsm_x4(uint32_t& r0, uint32_t& r1, uint32_t& r2,
                                        uint32_t& r3, const T* p) {
    asm volatile("ldmatrix.sync.aligned.m8n8.x4.shared.b16 {%0,%1,%2,%3}, [%4];\n"
                 : "=r"(r0), "=r"(r1), "=r"(r2), "=r"(r3) : "r"(smem_u32(p)));
}
__device__ __forceinline__ void mma_bf16(float d[4], const uint32_t a[4],
                                         const uint32_t b[2]) {
    asm volatile(
        "mma.sync.aligned.m16n8k16.row.col.f32.bf16.bf16.f32 "
        "{%0,%1,%2,%3}, {%4,%5,%6,%7}, {%8,%9}, {%0,%1,%2,%3};\n"
        : "+f"(d[0]), "+f"(d[1]), "+f"(d[2]), "+f"(d[3])
        : "r"(a[0]), "r"(a[1]), "r"(a[2]), "r"(a[3]), "r"(b[0]), "r"(b[1]));
}
__device__ __forceinline__ void mma_fp16(float d[4], const uint32_t a[4],
                                         const uint32_t b[2]) {
    asm volatile(
        "mma.sync.aligned.m16n8k16.row.col.f32.f16.f16.f32 "
        "{%0,%1,%2,%3}, {%4,%5,%6,%7}, {%8,%9}, {%0,%1,%2,%3};\n"
        : "+f"(d[0]), "+f"(d[1]), "+f"(d[2]), "+f"(d[3])
        : "r"(a[0]), "r"(a[1]), "r"(a[2]), "r"(a[3]), "r"(b[0]), "r"(b[1]));
}

// ---------------- RoPE tables (same math as reference; computed once) --------
__global__ void rope_tab(float* __restrict__ tc, float* __restrict__ ts, int T) {
    int i = blockIdx.x * blockDim.x + threadIdx.x;
    if (i >= T * (HD / 2)) return;
    int t = i / (HD / 2);
    int d = i % (HD / 2);
    float invf = 1.0f / powf(10000.0f, (float)d * (2.0f / (float)HD));
    float ang = (float)t * invf;
    tc[i] = cosf(ang);
    ts[i] = sinf(ang);
}

// ---------------- fused weight quantization -> fp16 --------------------------
__global__ void prep_w_all(const float* __restrict__ wq, const float* __restrict__ wk,
                           const float* __restrict__ wv, const float* __restrict__ wp,
                           __half* __restrict__ qkvf, __half* __restrict__ pf,
                           const float* __restrict__ sfp) {
    const int row = blockIdx.x;
    const float* wr;
    __half* of;
    if (row < 2048) {
        wr = wq + (size_t)row * DIM;            of = qkvf + (size_t)row * DIM;
    } else if (row < 2560) {
        wr = wk + (size_t)(row - 2048) * DIM;   of = qkvf + (size_t)row * DIM;
    } else if (row < 3072) {
        wr = wv + (size_t)(row - 2560) * DIM;   of = qkvf + (size_t)row * DIM;
    } else {
        wr = wp + (size_t)(row - 3072) * DIM;   of = pf + (size_t)(row - 3072) * DIM;
    }

    float part = 0.0f;
    for (int c = threadIdx.x; c < DIM; c += blockDim.x) part += fabsf(wr[c]);

    __shared__ float sh[8];
    #pragma unroll
    for (int off = 16; off; off >>= 1)
        part += __shfl_xor_sync(0xffffffffu, part, off);
    if ((threadIdx.x & 31) == 0) sh[threadIdx.x >> 5] = part;
    __syncthreads();
    float tot = 0.0f;
    #pragma unroll
    for (int i = 0; i < 8; i++) tot += sh[i];

    const float scale = fmaxf(tot * (1.0f / (float)DIM), 1e-8f);
    const float thr = 0.7f * scale;
    const float sf = *sfp;
    for (int c = threadIdx.x; c < DIM; c += blockDim.x) {
        float wv2 = wr[c];
        float wqv = (fabsf(wv2) > thr) ? copysignf(scale, wv2) : 0.0f;
        of[c] = __float2half_rn(wv2 + sf * (wqv - wv2));
    }
}

// ---------------- fp32 -> fp16 for activations -------------------------------
__global__ void split_act_h(const float* __restrict__ in, __half* __restrict__ out,
                            int n4) {
    int i = blockIdx.x * blockDim.x + threadIdx.x;
    if (i >= n4) return;
    float4 v = ((const float4*)in)[i];
    __half2 h01 = __floats2half2_rn(v.x, v.y);
    __half2 h23 = __floats2half2_rn(v.z, v.w);
    uint2 o;
    o.x = *(uint32_t*)&h01;
    o.y = *(uint32_t*)&h23;
    ((uint2*)out)[i] = o;
}

// ---------------- fp16 NT GEMM (BK=64, register-pipelined fragments) ---------
#define LDS_K 72
#define GSTG (128 * LDS_K)

__global__ __launch_bounds__(256, 2)
void gemm_nt_fp16(const __half* __restrict__ A, const __half* __restrict__ B,
                  float* __restrict__ C, int M, int N, int K) {
    extern __shared__ __half smh[];

    const int tid = threadIdx.x;
    const int lane = tid & 31;
    const int wm = (tid >> 5) & 1;
    const int wn = tid >> 6;
    const int m0 = blockIdx.y * 128;
    const int n0 = blockIdx.x * 128;

    float acc[4][4][4];
    #pragma unroll
    for (int i = 0; i < 4; i++)
        #pragma unroll
        for (int j = 0; j < 4; j++)
            #pragma unroll
            for (int r = 0; r < 4; r++) acc[i][j][r] = 0.0f;

    const int aoff = (wm * 64 + (lane & 15)) * LDS_K + (lane >> 4) * 8;
    const int boff = (wn * 32 + ((lane >> 4) & 1) * 8 + (lane & 7)) * LDS_K
                     + ((lane >> 3) & 1) * 8;

    const int ntiles = K / 64;

    auto load_stage = [&](int st, int k0) {
        __half* base = smh + st * 2 * GSTG;
        #pragma unroll
        for (int s2 = 0; s2 < 4; s2++) {
            int chunk = tid + s2 * 256;
            int row = chunk >> 3;
            int part = chunk & 7;
            size_t goA = (size_t)(m0 + row) * K + k0 + part * 8;
            size_t goB = (size_t)(n0 + row) * K + k0 + part * 8;
            int so = row * LDS_K + part * 8;
            cp16(base + so, A + goA);
            cp16(base + GSTG + so, B + goB);
        }
    };

    load_stage(0, 0);
    cp_commit();

    // double-buffered register fragments
    uint32_t af[2][4][4], bf[2][4][2];

    for (int kt = 0; kt < ntiles; kt++) {
        cp_wait<0>();
        __syncthreads();
        if (kt + 1 < ntiles) {
            load_stage((kt + 1) & 1, (kt + 1) * 64);
            cp_commit();
        }

        const __half* sA = smh + (kt & 1) * 2 * GSTG;
        const __half* sB = sA + GSTG;

        // prologue: fragments of slice 0
        {
            #pragma unroll
            for (int jp = 0; jp < 2; jp++)
                ldsm_x4(bf[0][2 * jp][0], bf[0][2 * jp][1], bf[0][2 * jp + 1][0],
                        bf[0][2 * jp + 1][1], sB + boff + jp * 16 * LDS_K);
            #pragma unroll
            for (int i = 0; i < 4; i++)
                ldsm_x4(af[0][i][0], af[0][i][1], af[0][i][2], af[0][i][3],
                        sA + aoff + i * 16 * LDS_K);
        }

        #pragma unroll
        for (int ks = 0; ks < 4; ks++) {
            const int cur = ks & 1;
            const int nxt = cur ^ 1;
            if (ks < 3) {
                const int ko = (ks + 1) * 16;
                #pragma unroll
                for (int jp = 0; jp < 2; jp++)
                    ldsm_x4(bf[nxt][2 * jp][0], bf[nxt][2 * jp][1],
                            bf[nxt][2 * jp + 1][0], bf[nxt][2 * jp + 1][1],
                            sB + boff + jp * 16 * LDS_K + ko);
                #pragma unroll
                for (int i = 0; i < 4; i++)
                    ldsm_x4(af[nxt][i][0], af[nxt][i][1], af[nxt][i][2], af[nxt][i][3],
                            sA + aoff + i * 16 * LDS_K + ko);
            }
            #pragma unroll
            for (int i = 0; i < 4; i++)
                #pragma unroll
                for (int j = 0; j < 4; j++) mma_fp16(acc[i][j], af[cur][i], bf[cur][j]);
        }
    }

    const int g = lane >> 2, tig = lane & 3;
    #pragma unroll
    for (int i = 0; i < 4; i++) {
        #pragma unroll
        for (int j = 0; j < 4; j++) {
            int row1 = m0 + wm * 64 + i * 16 + g;
            int col = n0 + wn * 32 + j * 8 + tig * 2;
            float2 lo = make_float2(acc[i][j][0], acc[i][j][1]);
            float2 hi = make_float2(acc[i][j][2], acc[i][j][3]);
            *(float2*)&C[(size_t)row1 * N + col] = lo;
            *(float2*)&C[(size_t)(row1 + 8) * N + col] = hi;
        }
    }
}

// ---------------- fused RMSNorm+RoPE (q,k) + vn, table-driven ----------------
__global__ void rope_vn(const float* __restrict__ qkv,
                        __nv_bfloat16* __restrict__ qh, __nv_bfloat16* __restrict__ ql,
                        __nv_bfloat16* __restrict__ kh, __nv_bfloat16* __restrict__ kl,
                        float* __restrict__ vn,
                        const float* __restrict__ gain,
                        const float* __restrict__ tc, const float* __restrict__ ts,
                        int T) {
    const int bt = blockIdx.x;
    const int sl = blockIdx.y;
    const int d = threadIdx.x;   // 128
    __shared__ float sh[4];

    if (sl >= NH + NKV) {
        const int kv = sl - NH - NKV;
        float v = qkv[(size_t)bt * QKVW + DIM + NKV * HD + kv * HD + d];
        float ss = v * v;
        #pragma unroll
        for (int off = 16; off; off >>= 1)
            ss += __shfl_xor_sync(0xffffffffu, ss, off);
        if ((d & 31) == 0) sh[d >> 5] = ss;
        __syncthreads();
        float tot = sh[0] + sh[1] + sh[2] + sh[3];
        vn[((size_t)bt * NKV + kv) * HD + d] = v / fmaxf(sqrtf(tot), 1e-12f);
        return;
    }

    const bool isq = (sl < NH);
    const int hh = isq ? sl : (sl - NH);
    const int heads = isq ? NH : NKV;
    const size_t ibase = (size_t)bt * QKVW + (isq ? 0 : DIM) + hh * HD;

    float v = qkv[ibase + d];
    float ss = v * v;
    #pragma unroll
    for (int off = 16; off; off >>= 1)
        ss += __shfl_xor_sync(0xffffffffu, ss, off);
    if ((d & 31) == 0) sh[d >> 5] = ss;
    __syncthreads();
    float tot = sh[0] + sh[1] + sh[2] + sh[3];
    float rs = rsqrtf(tot * (1.0f / (float)HD) + 1.1920928955078125e-07f);

    __shared__ float sn[HD];
    sn[d] = v * rs;
    __syncthreads();

    if (d < HD / 2) {
        const int b = bt / T;
        const int t = bt % T;
        const int ti = t * (HD / 2) + d;
        float c = tc[ti], s = ts[ti];
        float x1 = sn[d], x2 = sn[d + HD / 2];
        float gq = isq ? gain[hh] : 1.0f;
        float o1 = (x1 * c + x2 * s) * gq;
        float o2 = (x2 * c - x1 * s) * gq;
        size_t obase = ((size_t)(b * heads + hh) * T + t) * HD;
        __nv_bfloat16 h1, l1, h2, l2;
        split_bf16(o1, h1, l1);
        split_bf16(o2, h2, l2);
        __nv_bfloat16* oh = isq ? qh : kh;
        __nv_bfloat16* ol = isq ? ql : kl;
        oh[obase + d] = h1;          ol[obase + d] = l1;
        oh[obase + d + HD / 2] = h2; ol[obase + d + HD / 2] = l2;
    }
}

// ---------------- V: split + transpose to [b][kv][d][t] ---------------------
__global__ void split_v_t(const float* __restrict__ qkv,
                          __nv_bfloat16* __restrict__ vth, __nv_bfloat16* __restrict__ vtl,
                          int T) {
    __shared__ float tile[32][33];
    const int bkv = blockIdx.z;
    const int b = bkv / NKV, kv = bkv % NKV;
    const int t0 = blockIdx.x * 32, d0 = blockIdx.y * 32;
    const int tx = threadIdx.x, ty = threadIdx.y;

    #pragma unroll
    for (int k = 0; k < 4; k++) {
        int t = t0 + ty + k * 8;
        tile[ty + k * 8][tx] =
            qkv[(size_t)(b * T + t) * QKVW + DIM + NKV * HD + kv * HD + d0 + tx];
    }
    __syncthreads();
    #pragma unroll
    for (int k = 0; k < 4; k++) {
        int d = d0 + ty + k * 8;
        float val = tile[tx][ty + k * 8];
        __nv_bfloat16 h, l;
        split_bf16(val, h, l);
        size_t o = ((size_t)(b * NKV + kv) * HD + d) * T + t0 + tx;
        vth[o] = h;
        vtl[o] = l;
    }
}

// ---------------- causal flash attention (bf16 3-pass; fp16 y output) -------
#define ATT_QS 136
#define ATT_VS 72
#define KV_STG (64 * ATT_QS * 2 + 128 * ATT_VS * 2)

__global__ __launch_bounds__(256, 1)
void attn_mma(const __nv_bfloat16* __restrict__ qh, const __nv_bfloat16* __restrict__ ql,
              const __nv_bfloat16* __restrict__ kh, const __nv_bfloat16* __restrict__ kl,
              const __nv_bfloat16* __restrict__ vth, const __nv_bfloat16* __restrict__ vtl,
              const float* __restrict__ vn,
              __half* __restrict__ yf, int T) {
    extern __shared__ __nv_bfloat16 smem_b[];
    __nv_bfloat16* sQh = smem_b;
    __nv_bfloat16* sQl = sQh + 128 * ATT_QS;
    __nv_bfloat16* sKV = sQl + 128 * ATT_QS;

    const int qb = (gridDim.x - 1) - blockIdx.x;
    const int bh2 = blockIdx.y;
    const int b = bh2 / NH, h = bh2 % NH, kv = h / GRP;
    const int tid = threadIdx.x;
    const int w = tid >> 5, lane = tid & 31, g = lane >> 2, tig = lane & 3;

    const size_t kbase0 = (size_t)(b * NKV + kv) * T * HD;
    const size_t vbase0 = (size_t)(b * NKV + kv) * HD * T;

    auto load_kv = [&](int st, int kb) {
        __nv_bfloat16* base = sKV + st * KV_STG;
        __nv_bfloat16* bKh = base;
        __nv_bfloat16* bKl = base + 64 * ATT_QS;
        __nv_bfloat16* bVh = base + 2 * 64 * ATT_QS;
        __nv_bfloat16* bVl = bVh + 128 * ATT_VS;
        const size_t kbase = kbase0 + (size_t)kb * 64 * HD;
        #pragma unroll
        for (int s2 = 0; s2 < 4; s2++) {
            int idx = tid + s2 * 256;
            int r = idx >> 4, dp = (idx & 15) * 8;
            cp16(bKh + r * ATT_QS + dp, kh + kbase + (size_t)r * HD + dp);
            cp16(bKl + r * ATT_QS + dp, kl + kbase + (size_t)r * HD + dp);
        }
        const size_t vbase = vbase0 + (size_t)kb * 64;
        #pragma unroll
        for (int s2 = 0; s2 < 4; s2++) {
            int idx = tid + s2 * 256;
            int d = idx >> 3, kp = (idx & 7) * 8;
            cp16(bVh + d * ATT_VS + kp, vth + vbase + (size_t)d * T + kp);
            cp16(bVl + d * ATT_VS + kp, vtl + vbase + (size_t)d * T + kp);
        }
    };

    const int nkb = 2 * qb + 2;
    load_kv(0, 0);
    cp_commit();

    {
        const size_t qbase = ((size_t)(b * NH + h) * T + qb * 128) * HD;
        for (int idx = tid; idx < 128 * 16; idx += 256) {
            int r = idx >> 4, dp = (idx & 15) * 8;
            *(uint4*)&sQh[r * ATT_QS + dp] = *(const uint4*)&qh[qbase + (size_t)r * HD + dp];
            *(uint4*)&sQl[r * ATT_QS + dp] = *(const uint4*)&ql[qbase + (size_t)r * HD + dp];
        }
    }
    __syncthreads();

    const int arow = w * 16;
    const int qoff = (arow + (lane & 15)) * ATT_QS + (lane >> 4) * 8;
    const int koff_f = (((lane >> 4) & 1) * 8 + (lane & 7)) * ATT_QS + ((lane >> 3) & 1) * 8;
    const int voff_f = (((lane >> 4) & 1) * 8 + (lane & 7)) * ATT_VS + ((lane >> 3) & 1) * 8;

    uint32_t qfh[8][4], qfl[8][4];
    #pragma unroll
    for (int kc = 0; kc < 8; kc++) {
        ldsm_x4(qfh[kc][0], qfh[kc][1], qfh[kc][2], qfh[kc][3], sQh + qoff + kc * 16);
        ldsm_x4(qfl[kc][0], qfl[kc][1], qfl[kc][2], qfl[kc][3], sQl + qoff + kc * 16);
    }

    float m_i[2] = {-1e30f, -1e30f};
    float l_i[2] = {0.0f, 0.0f};
    float O[16][4];
    #pragma unroll
    for (int jt = 0; jt < 16; jt++)
        #pragma unroll
        for (int r = 0; r < 4; r++) O[jt][r] = 0.0f;

    const float sc = 0.08838834764831845f;

    for (int kb = 0; kb < nkb; kb++) {
        cp_wait<0>();
        __syncthreads();
        if (kb + 1 < nkb) {
            load_kv((kb + 1) & 1, kb + 1);
            cp_commit();
        }

        const __nv_bfloat16* bKh = sKV + (kb & 1) * KV_STG;
        const __nv_bfloat16* bKl = bKh + 64 * ATT_QS;
        const __nv_bfloat16* bVh = bKh + 2 * 64 * ATT_QS;
        const __nv_bfloat16* bVl = bVh + 128 * ATT_VS;

        float s[8][4];
        #pragma unroll
        for (int j = 0; j < 8; j++)
            #pragma unroll
            for (int r = 0; r < 4; r++) s[j][r] = 0.0f;

        #pragma unroll
        for (int kc = 0; kc < 8; kc++) {
            const int ko = kc * 16;
            #pragma unroll
            for (int jp = 0; jp < 4; jp++) {
                uint32_t kh4[4], kl4[4];
                ldsm_x4(kh4[0], kh4[1], kh4[2], kh4[3],
                        bKh + koff_f + jp * 16 * ATT_QS + ko);
                ldsm_x4(kl4[0], kl4[1], kl4[2], kl4[3],
                        bKl + koff_f + jp * 16 * ATT_QS + ko);
                mma_bf16(s[2 * jp],     qfh[kc], &kh4[0]);
                mma_bf16(s[2 * jp],     qfl[kc], &kh4[0]);
                mma_bf16(s[2 * jp],     qfh[kc], &kl4[0]);
                mma_bf16(s[2 * jp + 1], qfh[kc], &kh4[2]);
                mma_bf16(s[2 * jp + 1], qfl[kc], &kh4[2]);
                mma_bf16(s[2 * jp + 1], qfh[kc], &kl4[2]);
            }
        }

        const int row0 = qb * 128 + arow + g;
        const bool nomask = (kb * 64 + 63) <= (qb * 128 + arow);
        if (nomask) {
            #pragma unroll
            for (int j = 0; j < 8; j++)
                #pragma unroll
                for (int r = 0; r < 4; r++) s[j][r] *= sc;
        } else {
            #pragma unroll
            for (int j = 0; j < 8; j++) {
                const int c = kb * 64 + j * 8 + tig * 2;
                s[j][0] = (c     <= row0)     ? s[j][0] * sc : -1e30f;
                s[j][1] = (c + 1 <= row0)     ? s[j][1] * sc : -1e30f;
                s[j][2] = (c     <= row0 + 8) ? s[j][2] * sc : -1e30f;
                s[j][3] = (c + 1 <= row0 + 8) ? s[j][3] * sc : -1e30f;
            }
        }

        #pragma unroll
        for (int i = 0; i < 2; i++) {
            float rm = -1e30f;
            #pragma unroll
            for (int j = 0; j < 8; j++)
                rm = fmaxf(rm, fmaxf(s[j][2 * i], s[j][2 * i + 1]));
            rm = fmaxf(rm, __shfl_xor_sync(0xffffffffu, rm, 1));
            rm = fmaxf(rm, __shfl_xor_sync(0xffffffffu, rm, 2));
            const float mnew = fmaxf(m_i[i], rm);
            const float alpha = __expf(m_i[i] - mnew);
            float rs = 0.0f;
            #pragma unroll
            for (int j = 0; j < 8; j++) {
                s[j][2 * i]     = __expf(s[j][2 * i] - mnew);
                s[j][2 * i + 1] = __expf(s[j][2 * i + 1] - mnew);
                rs += s[j][2 * i] + s[j][2 * i + 1];
            }
            rs += __shfl_xor_sync(0xffffffffu, rs, 1);
            rs += __shfl_xor_sync(0xffffffffu, rs, 2);
            l_i[i] = l_i[i] * alpha + rs;
            m_i[i] = mnew;
            #pragma unroll
            for (int jt = 0; jt < 16; jt++) {
                O[jt][2 * i] *= alpha;
                O[jt][2 * i + 1] *= alpha;
            }
        }

        #pragma unroll
        for (int kc = 0; kc < 4; kc++) {
            const int ko = kc * 16;
            uint32_t ph[4], pl[4];
            split2_u32(s[2 * kc][0],     s[2 * kc][1],     ph[0], pl[0]);
            split2_u32(s[2 * kc][2],     s[2 * kc][3],     ph[1], pl[1]);
            split2_u32(s[2 * kc + 1][0], s[2 * kc + 1][1], ph[2], pl[2]);
            split2_u32(s[2 * kc + 1][2], s[2 * kc + 1][3], ph[3], pl[3]);
            #pragma unroll
            for (int jp = 0; jp < 8; jp++) {
                uint32_t vh4[4], vl4[4];
                ldsm_x4(vh4[0], vh4[1], vh4[2], vh4[3],
                        bVh + voff_f + jp * 16 * ATT_VS + ko);
                ldsm_x4(vl4[0], vl4[1], vl4[2], vl4[3],
                        bVl + voff_f + jp * 16 * ATT_VS + ko);
                mma_bf16(O[2 * jp],     ph, &vh4[0]);
                mma_bf16(O[2 * jp],     pl, &vh4[0]);
                mma_bf16(O[2 * jp],     ph, &vl4[0]);
                mma_bf16(O[2 * jp + 1], ph, &vh4[2]);
                mma_bf16(O[2 * jp + 1], pl, &vh4[2]);
                mma_bf16(O[2 * jp + 1], ph, &vl4[2]);
            }
        }
    }

    // ---- fused epilogue: y = y_attn - (y.vn)vn -> fp16 -------------------
    const float inv0 = 1.0f / l_i[0];
    const float inv1 = 1.0f / l_i[1];
    const int r0 = qb * 128 + arow + g;
    const size_t bt0 = (size_t)b * T + r0;
    const float* vn0p = vn + bt0 * (NKV * HD) + kv * HD;
    const float* vn1p = vn0p + (size_t)8 * (NKV * HD);

    float d0 = 0.0f, d1 = 0.0f;
    #pragma unroll
    for (int jt = 0; jt < 16; jt++) {
        const int col = jt * 8 + tig * 2;
        float2 w0 = *(const float2*)&vn0p[col];
        float2 w1 = *(const float2*)&vn1p[col];
        d0 += O[jt][0] * inv0 * w0.x + O[jt][1] * inv0 * w0.y;
        d1 += O[jt][2] * inv1 * w1.x + O[jt][3] * inv1 * w1.y;
    }
    d0 += __shfl_xor_sync(0xffffffffu, d0, 1);
    d0 += __shfl_xor_sync(0xffffffffu, d0, 2);
    d1 += __shfl_xor_sync(0xffffffffu, d1, 1);
    d1 += __shfl_xor_sync(0xffffffffu, d1, 2);

    #pragma unroll
    for (int jt = 0; jt < 16; jt++) {
        const int col = jt * 8 + tig * 2;
        float2 w0 = *(const float2*)&vn0p[col];
        float2 w1 = *(const float2*)&vn1p[col];
        __half2 p0 = __floats2half2_rn(O[jt][0] * inv0 - d0 * w0.x,
                                       O[jt][1] * inv0 - d0 * w0.y);
        __half2 p1 = __floats2half2_rn(O[jt][2] * inv1 - d1 * w1.x,
                                       O[jt][3] * inv1 - d1 * w1.y);
        *(uint32_t*)&yf[bt0 * DIM + h * HD + col] = *(uint32_t*)&p0;
        *(uint32_t*)&yf[(bt0 + 8) * DIM + h * HD + col] = *(uint32_t*)&p1;
    }
}

// ---------------- launcher ---------------------------------------------------
extern "C" void kernel_launch(void* const* d_in, const int* in_sizes, int n_in,
                              void* d_out, int out_size) {
    const float* x    = (const float*)d_in[0];
    const float* sfp  = (const float*)d_in[1];
    const float* wq   = (const float*)d_in[2];
    const float* wk   = (const float*)d_in[3];
    const float* wv   = (const float*)d_in[4];
    const float* wp   = (const float*)d_in[5];
    const float* gain = (const float*)d_in[6];

    const int BT = in_sizes[0] / DIM;
    const int T = TSEQ;
    const int Bb = BT / T;

    __half *pwqkvf, *pwpf, *paf;
    __nv_bfloat16 *pqh, *pql, *pkh, *pkl, *pvth, *pvtl;
    float *pqkv, *pvn, *ptc, *pts;
    cudaGetSymbolAddress((void**)&pwqkvf, g_wqkv_f);
    cudaGetSymbolAddress((void**)&pwpf, g_wp_f);
    cudaGetSymbolAddress((void**)&paf, g_a_f);
    cudaGetSymbolAddress((void**)&pqh, g_qh);
    cudaGetSymbolAddress((void**)&pql, g_ql);
    cudaGetSymbolAddress((void**)&pkh, g_kh);
    cudaGetSymbolAddress((void**)&pkl, g_kl);
    cudaGetSymbolAddress((void**)&pvth, g_vth);
    cudaGetSymbolAddress((void**)&pvtl, g_vtl);
    cudaGetSymbolAddress((void**)&pqkv, g_qkv);
    cudaGetSymbolAddress((void**)&pvn, g_vn);
    cudaGetSymbolAddress((void**)&ptc, g_ropec);
    cudaGetSymbolAddress((void**)&pts, g_ropes);

    // 1) effective weights -> fp16; rope tables
    prep_w_all<<<QKVW + DIM, 256>>>(wq, wk, wv, wp, pwqkvf, pwpf, sfp);
    rope_tab<<<(T * (HD / 2) + 255) / 256, 256>>>(ptc, pts, T);

    // 2) x -> fp16; merged QKV projection (N=3072)
    const int n4 = BT * DIM / 4;
    const size_t gsmem = (size_t)2 * 2 * GSTG * sizeof(__half);  // 73728
    cudaFuncSetAttribute(gemm_nt_fp16, cudaFuncAttributeMaxDynamicSharedMemorySize,
                         (int)gsmem);
    split_act_h<<<(n4 + 255) / 256, 256>>>(x, paf, n4);
    gemm_nt_fp16<<<dim3(QKVW / 128, BT / 128), 256, gsmem>>>(
        paf, pwqkvf, pqkv, BT, QKVW, DIM);

    // 3) fused rope(q,k) + vn (table-driven); V split+transpose
    rope_vn<<<dim3(BT, NH + 2 * NKV), 128>>>(pqkv, pqh, pql, pkh, pkl, pvn, gain,
                                             ptc, pts, T);
    split_v_t<<<dim3(T / 32, HD / 32, Bb * NKV), dim3(32, 8)>>>(pqkv, pvth, pvtl, T);

    // 4) attention (bf16 3-pass) + fused vorth -> fp16 y
    size_t asmem = (size_t)(2 * 128 * ATT_QS + 2 * KV_STG) * sizeof(__nv_bfloat16);
    cudaFuncSetAttribute(attn_mma, cudaFuncAttributeMaxDynamicSharedMemorySize, (int)asmem);
    attn_mma<<<dim3(T / 128, Bb * NH), 256, asmem>>>(
        pqh, pql, pkh, pkl, pvth, pvtl, pvn, paf, T);

    // 5) output projection -> d_out (fp16 single-pass)
    gemm_nt_fp16<<<dim3(DIM / 128, BT / 128), 256, gsmem>>>(
        paf, pwpf, (float*)d_out, BT, DIM, DIM);
}

// round 17
// speedup vs baseline: 1.0295x; 1.0295x over previous
#include <cuda_runtime.h>
#include <cuda_bf16.h>
#include <cuda_fp16.h>
#include <cstdint>
#include <math.h>

#define DIM  2048
#define NH   16
#define NKV  4
#define HD   128
#define GRP  (NH / NKV)
#define TSEQ 2048
#define BMAX 2
#define QKVW (DIM + 2 * NKV * HD)   // 3072

// ---------------- scratch (device globals; no allocation allowed) ----------
__device__ __half g_wqkv_f[QKVW * DIM];
__device__ __half g_wp_f[DIM * DIM];
__device__ __half g_a_f[BMAX * TSEQ * DIM];
__device__ float g_qkv[BMAX * TSEQ * QKVW];
__device__ float g_vn[BMAX * TSEQ * NKV * HD];
__device__ float g_ropec[TSEQ * (HD / 2)];
__device__ float g_ropes[TSEQ * (HD / 2)];
__device__ __nv_bfloat16 g_qh[BMAX * NH * TSEQ * HD];
__device__ __nv_bfloat16 g_ql[BMAX * NH * TSEQ * HD];
__device__ __nv_bfloat16 g_kh[BMAX * NKV * TSEQ * HD];
__device__ __nv_bfloat16 g_kl[BMAX * NKV * TSEQ * HD];
__device__ __nv_bfloat16 g_vth[BMAX * NKV * HD * TSEQ];
__device__ __nv_bfloat16 g_vtl[BMAX * NKV * HD * TSEQ];

__device__ __forceinline__ void split_bf16(float v, __nv_bfloat16& h, __nv_bfloat16& l) {
    h = __float2bfloat16_rn(v);
    l = __float2bfloat16_rn(v - __bfloat162float(h));
}

__device__ __forceinline__ void split2_u32(float x, float y, uint32_t& h, uint32_t& l) {
    __nv_bfloat162 hh = __floats2bfloat162_rn(x, y);
    float rx = x - __bfloat162float(hh.x);
    float ry = y - __bfloat162float(hh.y);
    __nv_bfloat162 ll = __floats2bfloat162_rn(rx, ry);
    h = *(uint32_t*)&hh;
    l = *(uint32_t*)&ll;
}

// ---------------- async copy / ldmatrix / mma helpers ------------------------
__device__ __forceinline__ uint32_t smem_u32(const void* p) {
    return (uint32_t)__cvta_generic_to_shared(p);
}
__device__ __forceinline__ void cp16(void* s, const void* g) {
    asm volatile("cp.async.cg.shared.global [%0], [%1], 16;\n"
                 :: "r"(smem_u32(s)), "l"(g));
}
__device__ __forceinline__ void cp_commit() {
    asm volatile("cp.async.commit_group;\n");
}
template <int N>
__device__ __forceinline__ void cp_wait() {
    asm volatile("cp.async.wait_group %0;\n" :: "n"(N));
}
template <typename T>
__device__ __forceinline__ void ldsm_x4(uint32_t& r0, uint32_t& r1, uint32_t& r2,
                                        uint32_t& r3, const T* p) {
    asm volatile("ldmatrix.sync.aligned.m8n8.x4.shared.b16 {%0,%1,%2,%3}, [%4];\n"
                 : "=r"(r0), "=r"(r1), "=r"(r2), "=r"(r3) : "r"(smem_u32(p)));
}
__device__ __forceinline__ void mma_bf16(float d[4], const uint32_t a[4],
                                         const uint32_t b[2]) {
    asm volatile(
        "mma.sync.aligned.m16n8k16.row.col.f32.bf16.bf16.f32 "
        "{%0,%1,%2,%3}, {%4,%5,%6,%7}, {%8,%9}, {%0,%1,%2,%3};\n"
        : "+f"(d[0]), "+f"(d[1]), "+f"(d[2]), "+f"(d[3])
        : "r"(a[0]), "r"(a[1]), "r"(a[2]), "r"(a[3]), "r"(b[0]), "r"(b[1]));
}
__device__ __forceinline__ void mma_fp16(float d[4], const uint32_t a[4],
                                         const uint32_t b[2]) {
    asm volatile(
        "mma.sync.aligned.m16n8k16.row.col.f32.f16.f16.f32 "
        "{%0,%1,%2,%3}, {%4,%5,%6,%7}, {%8,%9}, {%0,%1,%2,%3};\n"
        : "+f"(d[0]), "+f"(d[1]), "+f"(d[2]), "+f"(d[3])
        : "r"(a[0]), "r"(a[1]), "r"(a[2]), "r"(a[3]), "r"(b[0]), "r"(b[1]));
}

// ---------------- RoPE tables (same math as reference; computed once) --------
__global__ void rope_tab(float* __restrict__ tc, float* __restrict__ ts, int T) {
    int i = blockIdx.x * blockDim.x + threadIdx.x;
    if (i >= T * (HD / 2)) return;
    int t = i / (HD / 2);
    int d = i % (HD / 2);
    float invf = 1.0f / powf(10000.0f, (float)d * (2.0f / (float)HD));
    float ang = (float)t * invf;
    tc[i] = cosf(ang);
    ts[i] = sinf(ang);
}

// ---------------- fused weight quantization -> fp16 --------------------------
__global__ void prep_w_all(const float* __restrict__ wq, const float* __restrict__ wk,
                           const float* __restrict__ wv, const float* __restrict__ wp,
                           __half* __restrict__ qkvf, __half* __restrict__ pf,
                           const float* __restrict__ sfp) {
    const int row = blockIdx.x;
    const float* wr;
    __half* of;
    if (row < 2048) {
        wr = wq + (size_t)row * DIM;            of = qkvf + (size_t)row * DIM;
    } else if (row < 2560) {
        wr = wk + (size_t)(row - 2048) * DIM;   of = qkvf + (size_t)row * DIM;
    } else if (row < 3072) {
        wr = wv + (size_t)(row - 2560) * DIM;   of = qkvf + (size_t)row * DIM;
    } else {
        wr = wp + (size_t)(row - 3072) * DIM;   of = pf + (size_t)(row - 3072) * DIM;
    }

    float part = 0.0f;
    for (int c = threadIdx.x; c < DIM; c += blockDim.x) part += fabsf(wr[c]);

    __shared__ float sh[8];
    #pragma unroll
    for (int off = 16; off; off >>= 1)
        part += __shfl_xor_sync(0xffffffffu, part, off);
    if ((threadIdx.x & 31) == 0) sh[threadIdx.x >> 5] = part;
    __syncthreads();
    float tot = 0.0f;
    #pragma unroll
    for (int i = 0; i < 8; i++) tot += sh[i];

    const float scale = fmaxf(tot * (1.0f / (float)DIM), 1e-8f);
    const float thr = 0.7f * scale;
    const float sf = *sfp;
    for (int c = threadIdx.x; c < DIM; c += blockDim.x) {
        float wv2 = wr[c];
        float wqv = (fabsf(wv2) > thr) ? copysignf(scale, wv2) : 0.0f;
        of[c] = __float2half_rn(wv2 + sf * (wqv - wv2));
    }
}

// ---------------- fp32 -> fp16 for activations -------------------------------
__global__ void split_act_h(const float* __restrict__ in, __half* __restrict__ out,
                            int n4) {
    int i = blockIdx.x * blockDim.x + threadIdx.x;
    if (i >= n4) return;
    float4 v = ((const float4*)in)[i];
    __half2 h01 = __floats2half2_rn(v.x, v.y);
    __half2 h23 = __floats2half2_rn(v.z, v.w);
    uint2 o;
    o.x = *(uint32_t*)&h01;
    o.y = *(uint32_t*)&h23;
    ((uint2*)out)[i] = o;
}

// ---------------- fp16 single-pass tensor-core NT GEMM (R15 config) ----------
#define LDS_K 72
#define GSTG (128 * LDS_K)

__global__ __launch_bounds__(256, 2)
void gemm_nt_fp16(const __half* __restrict__ A, const __half* __restrict__ B,
                  float* __restrict__ C, int M, int N, int K) {
    extern __shared__ __half smh[];

    const int tid = threadIdx.x;
    const int lane = tid & 31;
    const int wm = (tid >> 5) & 1;
    const int wn = tid >> 6;
    const int m0 = blockIdx.y * 128;
    const int n0 = blockIdx.x * 128;

    float acc[4][4][4];
    #pragma unroll
    for (int i = 0; i < 4; i++)
        #pragma unroll
        for (int j = 0; j < 4; j++)
            #pragma unroll
            for (int r = 0; r < 4; r++) acc[i][j][r] = 0.0f;

    const int aoff = (wm * 64 + (lane & 15)) * LDS_K + (lane >> 4) * 8;
    const int boff = (wn * 32 + ((lane >> 4) & 1) * 8 + (lane & 7)) * LDS_K
                     + ((lane >> 3) & 1) * 8;

    const int ntiles = K / 64;

    auto load_stage = [&](int st, int k0) {
        __half* base = smh + st * 2 * GSTG;
        #pragma unroll
        for (int s2 = 0; s2 < 4; s2++) {
            int chunk = tid + s2 * 256;
            int row = chunk >> 3;
            int part = chunk & 7;
            size_t goA = (size_t)(m0 + row) * K + k0 + part * 8;
            size_t goB = (size_t)(n0 + row) * K + k0 + part * 8;
            int so = row * LDS_K + part * 8;
            cp16(base + so, A + goA);
            cp16(base + GSTG + so, B + goB);
        }
    };

    load_stage(0, 0);
    cp_commit();

    for (int kt = 0; kt < ntiles; kt++) {
        cp_wait<0>();
        __syncthreads();
        if (kt + 1 < ntiles) {
            load_stage((kt + 1) & 1, (kt + 1) * 64);
            cp_commit();
        }

        const __half* sA = smh + (kt & 1) * 2 * GSTG;
        const __half* sB = sA + GSTG;

        #pragma unroll
        for (int ks = 0; ks < 4; ks++) {
            const int ko = ks * 16;
            uint32_t af[4][4], bf_[4][2];

            #pragma unroll
            for (int jp = 0; jp < 2; jp++)
                ldsm_x4(bf_[2 * jp][0], bf_[2 * jp][1], bf_[2 * jp + 1][0],
                        bf_[2 * jp + 1][1], sB + boff + jp * 16 * LDS_K + ko);
            #pragma unroll
            for (int i = 0; i < 4; i++)
                ldsm_x4(af[i][0], af[i][1], af[i][2], af[i][3],
                        sA + aoff + i * 16 * LDS_K + ko);
            #pragma unroll
            for (int i = 0; i < 4; i++)
                #pragma unroll
                for (int j = 0; j < 4; j++) mma_fp16(acc[i][j], af[i], bf_[j]);
        }
    }

    const int g = lane >> 2, tig = lane & 3;
    #pragma unroll
    for (int i = 0; i < 4; i++) {
        #pragma unroll
        for (int j = 0; j < 4; j++) {
            int row1 = m0 + wm * 64 + i * 16 + g;
            int col = n0 + wn * 32 + j * 8 + tig * 2;
            float2 lo = make_float2(acc[i][j][0], acc[i][j][1]);
            float2 hi = make_float2(acc[i][j][2], acc[i][j][3]);
            *(float2*)&C[(size_t)row1 * N + col] = lo;
            *(float2*)&C[(size_t)(row1 + 8) * N + col] = hi;
        }
    }
}

// ---------------- fused RMSNorm+RoPE (q,k) + vn, table-driven ----------------
__global__ void rope_vn(const float* __restrict__ qkv,
                        __nv_bfloat16* __restrict__ qh, __nv_bfloat16* __restrict__ ql,
                        __nv_bfloat16* __restrict__ kh, __nv_bfloat16* __restrict__ kl,
                        float* __restrict__ vn,
                        const float* __restrict__ gain,
                        const float* __restrict__ tc, const float* __restrict__ ts,
                        int T) {
    const int bt = blockIdx.x;
    const int sl = blockIdx.y;
    const int d = threadIdx.x;   // 128
    __shared__ float sh[4];

    if (sl >= NH + NKV) {
        const int kv = sl - NH - NKV;
        float v = qkv[(size_t)bt * QKVW + DIM + NKV * HD + kv * HD + d];
        float ss = v * v;
        #pragma unroll
        for (int off = 16; off; off >>= 1)
            ss += __shfl_xor_sync(0xffffffffu, ss, off);
        if ((d & 31) == 0) sh[d >> 5] = ss;
        __syncthreads();
        float tot = sh[0] + sh[1] + sh[2] + sh[3];
        vn[((size_t)bt * NKV + kv) * HD + d] = v / fmaxf(sqrtf(tot), 1e-12f);
        return;
    }

    const bool isq = (sl < NH);
    const int hh = isq ? sl : (sl - NH);
    const int heads = isq ? NH : NKV;
    const size_t ibase = (size_t)bt * QKVW + (isq ? 0 : DIM) + hh * HD;

    float v = qkv[ibase + d];
    float ss = v * v;
    #pragma unroll
    for (int off = 16; off; off >>= 1)
        ss += __shfl_xor_sync(0xffffffffu, ss, off);
    if ((d & 31) == 0) sh[d >> 5] = ss;
    __syncthreads();
    float tot = sh[0] + sh[1] + sh[2] + sh[3];
    float rs = rsqrtf(tot * (1.0f / (float)HD) + 1.1920928955078125e-07f);

    __shared__ float sn[HD];
    sn[d] = v * rs;
    __syncthreads();

    if (d < HD / 2) {
        const int b = bt / T;
        const int t = bt % T;
        const int ti = t * (HD / 2) + d;
        float c = tc[ti], s = ts[ti];
        float x1 = sn[d], x2 = sn[d + HD / 2];
        float gq = isq ? gain[hh] : 1.0f;
        float o1 = (x1 * c + x2 * s) * gq;
        float o2 = (x2 * c - x1 * s) * gq;
        size_t obase = ((size_t)(b * heads + hh) * T + t) * HD;
        __nv_bfloat16 h1, l1, h2, l2;
        split_bf16(o1, h1, l1);
        split_bf16(o2, h2, l2);
        __nv_bfloat16* oh = isq ? qh : kh;
        __nv_bfloat16* ol = isq ? ql : kl;
        oh[obase + d] = h1;          ol[obase + d] = l1;
        oh[obase + d + HD / 2] = h2; ol[obase + d + HD / 2] = l2;
    }
}

// ---------------- V: split + transpose to [b][kv][d][t] ---------------------
__global__ void split_v_t(const float* __restrict__ qkv,
                          __nv_bfloat16* __restrict__ vth, __nv_bfloat16* __restrict__ vtl,
                          int T) {
    __shared__ float tile[32][33];
    const int bkv = blockIdx.z;
    const int b = bkv / NKV, kv = bkv % NKV;
    const int t0 = blockIdx.x * 32, d0 = blockIdx.y * 32;
    const int tx = threadIdx.x, ty = threadIdx.y;

    #pragma unroll
    for (int k = 0; k < 4; k++) {
        int t = t0 + ty + k * 8;
        tile[ty + k * 8][tx] =
            qkv[(size_t)(b * T + t) * QKVW + DIM + NKV * HD + kv * HD + d0 + tx];
    }
    __syncthreads();
    #pragma unroll
    for (int k = 0; k < 4; k++) {
        int d = d0 + ty + k * 8;
        float val = tile[tx][ty + k * 8];
        __nv_bfloat16 h, l;
        split_bf16(val, h, l);
        size_t o = ((size_t)(b * NKV + kv) * HD + d) * T + t0 + tx;
        vth[o] = h;
        vtl[o] = l;
    }
}

// ---------------- causal flash attention (3-stage KV pipe, Q from gmem) -----
#define ATT_QS 136
#define ATT_VS 72
#define KV_STG (64 * ATT_QS * 2 + 128 * ATT_VS * 2)   // halfs per stage

__global__ __launch_bounds__(256, 1)
void attn_mma(const __nv_bfloat16* __restrict__ qh, const __nv_bfloat16* __restrict__ ql,
              const __nv_bfloat16* __restrict__ kh, const __nv_bfloat16* __restrict__ kl,
              const __nv_bfloat16* __restrict__ vth, const __nv_bfloat16* __restrict__ vtl,
              const float* __restrict__ vn,
              __half* __restrict__ yf, int T) {
    extern __shared__ __nv_bfloat16 smem_b[];
    __nv_bfloat16* sKV = smem_b;   // 3 stages

    const int qb = (gridDim.x - 1) - blockIdx.x;
    const int bh2 = blockIdx.y;
    const int b = bh2 / NH, h = bh2 % NH, kv = h / GRP;
    const int tid = threadIdx.x;
    const int w = tid >> 5, lane = tid & 31, g = lane >> 2, tig = lane & 3;

    const size_t kbase0 = (size_t)(b * NKV + kv) * T * HD;
    const size_t vbase0 = (size_t)(b * NKV + kv) * HD * T;

    auto load_kv = [&](int st, int kb) {
        __nv_bfloat16* base = sKV + st * KV_STG;
        __nv_bfloat16* bKh = base;
        __nv_bfloat16* bKl = base + 64 * ATT_QS;
        __nv_bfloat16* bVh = base + 2 * 64 * ATT_QS;
        __nv_bfloat16* bVl = bVh + 128 * ATT_VS;
        const size_t kbase = kbase0 + (size_t)kb * 64 * HD;
        #pragma unroll
        for (int s2 = 0; s2 < 4; s2++) {
            int idx = tid + s2 * 256;
            int r = idx >> 4, dp = (idx & 15) * 8;
            cp16(bKh + r * ATT_QS + dp, kh + kbase + (size_t)r * HD + dp);
            cp16(bKl + r * ATT_QS + dp, kl + kbase + (size_t)r * HD + dp);
        }
        const size_t vbase = vbase0 + (size_t)kb * 64;
        #pragma unroll
        for (int s2 = 0; s2 < 4; s2++) {
            int idx = tid + s2 * 256;
            int d = idx >> 3, kp = (idx & 7) * 8;
            cp16(bVh + d * ATT_VS + kp, vth + vbase + (size_t)d * T + kp);
            cp16(bVl + d * ATT_VS + kp, vtl + vbase + (size_t)d * T + kp);
        }
    };

    const int nkb = 2 * qb + 2;
    load_kv(0, 0);
    cp_commit();
    load_kv(1, 1);     // nkb >= 2 always
    cp_commit();

    const int arow = w * 16;
    const int koff_f = (((lane >> 4) & 1) * 8 + (lane & 7)) * ATT_QS + ((lane >> 3) & 1) * 8;
    const int voff_f = (((lane >> 4) & 1) * 8 + (lane & 7)) * ATT_VS + ((lane >> 3) & 1) * 8;

    // Q fragments loaded straight from gmem in m16k16 A-fragment layout
    uint32_t qfh[8][4], qfl[8][4];
    {
        const size_t qrow0 = ((size_t)(b * NH + h) * T + qb * 128 + arow + g) * HD;
        const size_t qrow1 = qrow0 + (size_t)8 * HD;
        const int col0 = tig * 2;
        #pragma unroll
        for (int kc = 0; kc < 8; kc++) {
            const int c = kc * 16 + col0;
            qfh[kc][0] = *(const uint32_t*)&qh[qrow0 + c];
            qfh[kc][1] = *(const uint32_t*)&qh[qrow1 + c];
            qfh[kc][2] = *(const uint32_t*)&qh[qrow0 + c + 8];
            qfh[kc][3] = *(const uint32_t*)&qh[qrow1 + c + 8];
            qfl[kc][0] = *(const uint32_t*)&ql[qrow0 + c];
            qfl[kc][1] = *(const uint32_t*)&ql[qrow1 + c];
            qfl[kc][2] = *(const uint32_t*)&ql[qrow0 + c + 8];
            qfl[kc][3] = *(const uint32_t*)&ql[qrow1 + c + 8];
        }
    }

    float m_i[2] = {-1e30f, -1e30f};
    float l_i[2] = {0.0f, 0.0f};
    float O[16][4];
    #pragma unroll
    for (int jt = 0; jt < 16; jt++)
        #pragma unroll
        for (int r = 0; r < 4; r++) O[jt][r] = 0.0f;

    const float sc = 0.08838834764831845f;

    for (int kb = 0; kb < nkb; kb++) {
        if (kb + 1 < nkb) {
            cp_wait<1>();   // stage kb landed (kb+1 may still be in flight)
        } else {
            cp_wait<0>();
        }
        __syncthreads();    // everyone done with stage (kb+2)%3 (read in iter kb-1)
        if (kb + 2 < nkb) {
            load_kv((kb + 2) % 3, kb + 2);
            cp_commit();
        }

        const __nv_bfloat16* bKh = sKV + (kb % 3) * KV_STG;
        const __nv_bfloat16* bKl = bKh + 64 * ATT_QS;
        const __nv_bfloat16* bVh = bKh + 2 * 64 * ATT_QS;
        const __nv_bfloat16* bVl = bVh + 128 * ATT_VS;

        float s[8][4];
        #pragma unroll
        for (int j = 0; j < 8; j++)
            #pragma unroll
            for (int r = 0; r < 4; r++) s[j][r] = 0.0f;

        #pragma unroll
        for (int kc = 0; kc < 8; kc++) {
            const int ko = kc * 16;
            #pragma unroll
            for (int jp = 0; jp < 4; jp++) {
                uint32_t kh4[4], kl4[4];
                ldsm_x4(kh4[0], kh4[1], kh4[2], kh4[3],
                        bKh + koff_f + jp * 16 * ATT_QS + ko);
                ldsm_x4(kl4[0], kl4[1], kl4[2], kl4[3],
                        bKl + koff_f + jp * 16 * ATT_QS + ko);
                mma_bf16(s[2 * jp],     qfh[kc], &kh4[0]);
                mma_bf16(s[2 * jp],     qfl[kc], &kh4[0]);
                mma_bf16(s[2 * jp],     qfh[kc], &kl4[0]);
                mma_bf16(s[2 * jp + 1], qfh[kc], &kh4[2]);
                mma_bf16(s[2 * jp + 1], qfl[kc], &kh4[2]);
                mma_bf16(s[2 * jp + 1], qfh[kc], &kl4[2]);
            }
        }

        const int row0 = qb * 128 + arow + g;
        const bool nomask = (kb * 64 + 63) <= (qb * 128 + arow);
        if (nomask) {
            #pragma unroll
            for (int j = 0; j < 8; j++)
                #pragma unroll
                for (int r = 0; r < 4; r++) s[j][r] *= sc;
        } else {
            #pragma unroll
            for (int j = 0; j < 8; j++) {
                const int c = kb * 64 + j * 8 + tig * 2;
                s[j][0] = (c     <= row0)     ? s[j][0] * sc : -1e30f;
                s[j][1] = (c + 1 <= row0)     ? s[j][1] * sc : -1e30f;
                s[j][2] = (c     <= row0 + 8) ? s[j][2] * sc : -1e30f;
                s[j][3] = (c + 1 <= row0 + 8) ? s[j][3] * sc : -1e30f;
            }
        }

        #pragma unroll
        for (int i = 0; i < 2; i++) {
            float rm = -1e30f;
            #pragma unroll
            for (int j = 0; j < 8; j++)
                rm = fmaxf(rm, fmaxf(s[j][2 * i], s[j][2 * i + 1]));
            rm = fmaxf(rm, __shfl_xor_sync(0xffffffffu, rm, 1));
            rm = fmaxf(rm, __shfl_xor_sync(0xffffffffu, rm, 2));
            const float mnew = fmaxf(m_i[i], rm);
            const float alpha = __expf(m_i[i] - mnew);
            float rs = 0.0f;
            #pragma unroll
            for (int j = 0; j < 8; j++) {
                s[j][2 * i]     = __expf(s[j][2 * i] - mnew);
                s[j][2 * i + 1] = __expf(s[j][2 * i + 1] - mnew);
                rs += s[j][2 * i] + s[j][2 * i + 1];
            }
            rs += __shfl_xor_sync(0xffffffffu, rs, 1);
            rs += __shfl_xor_sync(0xffffffffu, rs, 2);
            l_i[i] = l_i[i] * alpha + rs;
            m_i[i] = mnew;
            #pragma unroll
            for (int jt = 0; jt < 16; jt++) {
                O[jt][2 * i] *= alpha;
                O[jt][2 * i + 1] *= alpha;
            }
        }

        #pragma unroll
        for (int kc = 0; kc < 4; kc++) {
            const int ko = kc * 16;
            uint32_t ph[4], pl[4];
            split2_u32(s[2 * kc][0],     s[2 * kc][1],     ph[0], pl[0]);
            split2_u32(s[2 * kc][2],     s[2 * kc][3],     ph[1], pl[1]);
            split2_u32(s[2 * kc + 1][0], s[2 * kc + 1][1], ph[2], pl[2]);
            split2_u32(s[2 * kc + 1][2], s[2 * kc + 1][3], ph[3], pl[3]);
            #pragma unroll
            for (int jp = 0; jp < 8; jp++) {
                uint32_t vh4[4], vl4[4];
                ldsm_x4(vh4[0], vh4[1], vh4[2], vh4[3],
                        bVh + voff_f + jp * 16 * ATT_VS + ko);
                ldsm_x4(vl4[0], vl4[1], vl4[2], vl4[3],
                        bVl + voff_f + jp * 16 * ATT_VS + ko);
                mma_bf16(O[2 * jp],     ph, &vh4[0]);
                mma_bf16(O[2 * jp],     pl, &vh4[0]);
                mma_bf16(O[2 * jp],     ph, &vl4[0]);
                mma_bf16(O[2 * jp + 1], ph, &vh4[2]);
                mma_bf16(O[2 * jp + 1], pl, &vh4[2]);
                mma_bf16(O[2 * jp + 1], ph, &vl4[2]);
            }
        }
    }

    // ---- fused epilogue: y = y_attn - (y.vn)vn -> fp16 -------------------
    const float inv0 = 1.0f / l_i[0];
    const float inv1 = 1.0f / l_i[1];
    const int r0 = qb * 128 + arow + g;
    const size_t bt0 = (size_t)b * T + r0;
    const float* vn0p = vn + bt0 * (NKV * HD) + kv * HD;
    const float* vn1p = vn0p + (size_t)8 * (NKV * HD);

    float d0 = 0.0f, d1 = 0.0f;
    #pragma unroll
    for (int jt = 0; jt < 16; jt++) {
        const int col = jt * 8 + tig * 2;
        float2 w0 = *(const float2*)&vn0p[col];
        float2 w1 = *(const float2*)&vn1p[col];
        d0 += O[jt][0] * inv0 * w0.x + O[jt][1] * inv0 * w0.y;
        d1 += O[jt][2] * inv1 * w1.x + O[jt][3] * inv1 * w1.y;
    }
    d0 += __shfl_xor_sync(0xffffffffu, d0, 1);
    d0 += __shfl_xor_sync(0xffffffffu, d0, 2);
    d1 += __shfl_xor_sync(0xffffffffu, d1, 1);
    d1 += __shfl_xor_sync(0xffffffffu, d1, 2);

    #pragma unroll
    for (int jt = 0; jt < 16; jt++) {
        const int col = jt * 8 + tig * 2;
        float2 w0 = *(const float2*)&vn0p[col];
        float2 w1 = *(const float2*)&vn1p[col];
        __half2 p0 = __floats2half2_rn(O[jt][0] * inv0 - d0 * w0.x,
                                       O[jt][1] * inv0 - d0 * w0.y);
        __half2 p1 = __floats2half2_rn(O[jt][2] * inv1 - d1 * w1.x,
                                       O[jt][3] * inv1 - d1 * w1.y);
        *(uint32_t*)&yf[bt0 * DIM + h * HD + col] = *(uint32_t*)&p0;
        *(uint32_t*)&yf[(bt0 + 8) * DIM + h * HD + col] = *(uint32_t*)&p1;
    }
}

// ---------------- launcher ---------------------------------------------------
extern "C" void kernel_launch(void* const* d_in, const int* in_sizes, int n_in,
                              void* d_out, int out_size) {
    const float* x    = (const float*)d_in[0];
    const float* sfp  = (const float*)d_in[1];
    const float* wq   = (const float*)d_in[2];
    const float* wk   = (const float*)d_in[3];
    const float* wv   = (const float*)d_in[4];
    const float* wp   = (const float*)d_in[5];
    const float* gain = (const float*)d_in[6];

    const int BT = in_sizes[0] / DIM;
    const int T = TSEQ;
    const int Bb = BT / T;

    __half *pwqkvf, *pwpf, *paf;
    __nv_bfloat16 *pqh, *pql, *pkh, *pkl, *pvth, *pvtl;
    float *pqkv, *pvn, *ptc, *pts;
    cudaGetSymbolAddress((void**)&pwqkvf, g_wqkv_f);
    cudaGetSymbolAddress((void**)&pwpf, g_wp_f);
    cudaGetSymbolAddress((void**)&paf, g_a_f);
    cudaGetSymbolAddress((void**)&pqh, g_qh);
    cudaGetSymbolAddress((void**)&pql, g_ql);
    cudaGetSymbolAddress((void**)&pkh, g_kh);
    cudaGetSymbolAddress((void**)&pkl, g_kl);
    cudaGetSymbolAddress((void**)&pvth, g_vth);
    cudaGetSymbolAddress((void**)&pvtl, g_vtl);
    cudaGetSymbolAddress((void**)&pqkv, g_qkv);
    cudaGetSymbolAddress((void**)&pvn, g_vn);
    cudaGetSymbolAddress((void**)&ptc, g_ropec);
    cudaGetSymbolAddress((void**)&pts, g_ropes);

    // 1) effective weights -> fp16; rope tables
    prep_w_all<<<QKVW + DIM, 256>>>(wq, wk, wv, wp, pwqkvf, pwpf, sfp);
    rope_tab<<<(T * (HD / 2) + 255) / 256, 256>>>(ptc, pts, T);

    // 2) x -> fp16; merged QKV projection (N=3072)
    const int n4 = BT * DIM / 4;
    const size_t gsmem = (size_t)2 * 2 * GSTG * sizeof(__half);  // 73728
    cudaFuncSetAttribute(gemm_nt_fp16, cudaFuncAttributeMaxDynamicSharedMemorySize,
                         (int)gsmem);
    split_act_h<<<(n4 + 255) / 256, 256>>>(x, paf, n4);
    gemm_nt_fp16<<<dim3(QKVW / 128, BT / 128), 256, gsmem>>>(
        paf, pwqkvf, pqkv, BT, QKVW, DIM);

    // 3) fused rope(q,k) + vn (table-driven); V split+transpose
    rope_vn<<<dim3(BT, NH + 2 * NKV), 128>>>(pqkv, pqh, pql, pkh, pkl, pvn, gain,
                                             ptc, pts, T);
    split_v_t<<<dim3(T / 32, HD / 32, Bb * NKV), dim3(32, 8)>>>(pqkv, pvth, pvtl, T);

    // 4) attention (bf16 3-pass, 3-stage KV pipeline) + fused vorth -> fp16 y
    size_t asmem = (size_t)(3 * KV_STG) * sizeof(__nv_bfloat16);   // 215040
    cudaFuncSetAttribute(attn_mma, cudaFuncAttributeMaxDynamicSharedMemorySize, (int)asmem);
    attn_mma<<<dim3(T / 128, Bb * NH), 256, asmem>>>(
        pqh, pql, pkh, pkl, pvth, pvtl, pvn, paf, T);

    // 5) output projection -> d_out (fp16 single-pass)
    gemm_nt_fp16<<<dim3(DIM / 128, BT / 128), 256, gsmem>>>(
        paf, pwpf, (float*)d_out, BT, DIM, DIM);
}